// round 4
// baseline (speedup 1.0000x reference)
#include <cuda_runtime.h>
#include <cstddef>

// Problem dims (compile-time)
#define Bz 512
#define Tz 128
#define Iz 512
#define Hz 512
#define Cz 97
#define Sz 26
#define XI (Iz + Cz)   // 609

// ---------------------------------------------------------------------------
// Scratch (device globals; no runtime allocation allowed)
// ---------------------------------------------------------------------------
__device__ alignas(16) float g_feat[(size_t)Bz * Tz * Hz];   // [B,T,H] projected encoder feats
__device__ alignas(16) float g_h[Bz * Hz];
__device__ alignas(16) float g_c[Bz * Hz];
__device__ alignas(16) float g_hp[Bz * Hz];
__device__ alignas(16) float g_ctx[Bz * Iz];
__device__ alignas(16) float g_gates[Bz * 4 * Hz];
__device__ alignas(16) float g_outh[(size_t)Bz * Sz * Hz];   // [B,S,H]

// ---------------------------------------------------------------------------
// init: zero h, c
// ---------------------------------------------------------------------------
__global__ void init_kernel() {
    int i = blockIdx.x * blockDim.x + threadIdx.x;
    if (i < Bz * Hz) { g_h[i] = 0.f; g_c[i] = 0.f; }
}

// ---------------------------------------------------------------------------
// Generic SGEMM:  C[m,n] = sum_k A[m,k] * B[n,k]  (+ bias[n])
// 128x128 tile, 256 threads, 8x8 per thread, BK=8.  Requires K % 8 == 0 and
// 16B-aligned rows of A and B (lda, ldb multiples of 4).  M/N guarded.
// ---------------------------------------------------------------------------
__global__ __launch_bounds__(256) void sgemm128(
    const float* __restrict__ A, const float* __restrict__ B,
    const float* __restrict__ bias, float* __restrict__ C,
    int M, int N, int K, int lda, int ldb, int ldc)
{
    __shared__ float As[8][128];
    __shared__ float Bs[8][128];
    const int tid = threadIdx.x;
    const int m0 = blockIdx.y * 128;
    const int n0 = blockIdx.x * 128;
    const int lr = tid >> 1;           // 0..127
    const int lc = (tid & 1) << 2;     // 0 or 4
    const int tx = tid & 15;
    const int ty = tid >> 4;

    float acc[8][8];
#pragma unroll
    for (int u = 0; u < 8; u++)
#pragma unroll
        for (int v = 0; v < 8; v++) acc[u][v] = 0.f;

    const int am = m0 + lr;
    const int bn = n0 + lr;

    for (int k0 = 0; k0 < K; k0 += 8) {
        float4 a4 = make_float4(0.f, 0.f, 0.f, 0.f);
        float4 b4 = make_float4(0.f, 0.f, 0.f, 0.f);
        if (am < M) a4 = *(const float4*)(A + (size_t)am * lda + k0 + lc);
        if (bn < N) b4 = *(const float4*)(B + (size_t)bn * ldb + k0 + lc);
        __syncthreads();
        As[lc + 0][lr] = a4.x; As[lc + 1][lr] = a4.y;
        As[lc + 2][lr] = a4.z; As[lc + 3][lr] = a4.w;
        Bs[lc + 0][lr] = b4.x; Bs[lc + 1][lr] = b4.y;
        Bs[lc + 2][lr] = b4.z; Bs[lc + 3][lr] = b4.w;
        __syncthreads();
#pragma unroll
        for (int kk = 0; kk < 8; kk++) {
            float4 a0 = *(const float4*)&As[kk][ty * 8];
            float4 a1 = *(const float4*)&As[kk][ty * 8 + 4];
            float4 b0 = *(const float4*)&Bs[kk][tx * 8];
            float4 b1 = *(const float4*)&Bs[kk][tx * 8 + 4];
            float ar[8] = {a0.x, a0.y, a0.z, a0.w, a1.x, a1.y, a1.z, a1.w};
            float br[8] = {b0.x, b0.y, b0.z, b0.w, b1.x, b1.y, b1.z, b1.w};
#pragma unroll
            for (int u = 0; u < 8; u++)
#pragma unroll
                for (int v = 0; v < 8; v++)
                    acc[u][v] = fmaf(ar[u], br[v], acc[u][v]);
        }
    }

#pragma unroll
    for (int u = 0; u < 8; u++) {
        int m = m0 + ty * 8 + u;
        if (m >= M) continue;
#pragma unroll
        for (int v = 0; v < 8; v++) {
            int n = n0 + tx * 8 + v;
            if (n < N) {
                float bv = bias ? bias[n] : 0.f;
                C[(size_t)m * ldc + n] = acc[u][v] + bv;
            }
        }
    }
}

// ---------------------------------------------------------------------------
// 64x64-tile SGEMM (no guards; dims must divide).  Used for hp.
// C[m,n] = sum_k A[m,k]*B[n,k] + bias[n]
// ---------------------------------------------------------------------------
__global__ __launch_bounds__(256) void gemm64(
    const float* __restrict__ A, const float* __restrict__ B,
    const float* __restrict__ bias, float* __restrict__ C,
    int K, int lda, int ldb, int ldc)
{
    __shared__ float As[16][65];
    __shared__ float Bs[16][65];
    const int tid = threadIdx.x;
    const int tx = tid & 15, ty = tid >> 4;
    const int m0 = blockIdx.y * 64, n0 = blockIdx.x * 64;
    float acc[4][4] = {};

    for (int k0 = 0; k0 < K; k0 += 16) {
        __syncthreads();
#pragma unroll
        for (int i = 0; i < 4; i++) {
            int idx = tid + i * 256;
            int r = idx >> 4, kk = idx & 15;
            As[kk][r] = A[(size_t)(m0 + r) * lda + k0 + kk];
            Bs[kk][r] = B[(size_t)(n0 + r) * ldb + k0 + kk];
        }
        __syncthreads();
#pragma unroll
        for (int kk = 0; kk < 16; kk++) {
            float ar[4], br[4];
#pragma unroll
            for (int u = 0; u < 4; u++) ar[u] = As[kk][ty * 4 + u];
#pragma unroll
            for (int v = 0; v < 4; v++) br[v] = Bs[kk][tx * 4 + v];
#pragma unroll
            for (int u = 0; u < 4; u++)
#pragma unroll
                for (int v = 0; v < 4; v++)
                    acc[u][v] = fmaf(ar[u], br[v], acc[u][v]);
        }
    }
#pragma unroll
    for (int u = 0; u < 4; u++) {
        int m = m0 + ty * 4 + u;
#pragma unroll
        for (int v = 0; v < 4; v++) {
            int n = n0 + tx * 4 + v;
            C[(size_t)m * ldc + n] = acc[u][v] + bias[n];
        }
    }
}

// ---------------------------------------------------------------------------
// Gates: gates[b,j] = sum_i ctx[b,i]*W_ih[j,i] + W_ih[j, I+cls(b)]
//                   + sum_k h[b,k]*W_hh[j,k] + b_ih[j] + b_hh[j]
// M=512, N=2048, K=512 twice.  64x64 tiles -> 256 blocks.
// ---------------------------------------------------------------------------
__global__ __launch_bounds__(256) void gates_kernel(
    const float* __restrict__ W_ih, const float* __restrict__ W_hh,
    const float* __restrict__ b_ih, const float* __restrict__ b_hh,
    const int* __restrict__ text, int step)
{
    __shared__ float As[16][65];
    __shared__ float Bs[16][65];
    const int tid = threadIdx.x;
    const int tx = tid & 15, ty = tid >> 4;
    const int m0 = blockIdx.y * 64, n0 = blockIdx.x * 64;
    float acc[4][4] = {};

#pragma unroll 1
    for (int pass = 0; pass < 2; pass++) {
        const float* A = pass ? g_h : g_ctx;
        const float* Bm = pass ? W_hh : W_ih;
        const int ldb = pass ? Hz : XI;
        for (int k0 = 0; k0 < 512; k0 += 16) {
            __syncthreads();
#pragma unroll
            for (int i = 0; i < 4; i++) {
                int idx = tid + i * 256;
                int r = idx >> 4, kk = idx & 15;
                As[kk][r] = A[(size_t)(m0 + r) * Hz + k0 + kk];
                Bs[kk][r] = Bm[(size_t)(n0 + r) * ldb + k0 + kk];
            }
            __syncthreads();
#pragma unroll
            for (int kk = 0; kk < 16; kk++) {
                float ar[4], br[4];
#pragma unroll
                for (int u = 0; u < 4; u++) ar[u] = As[kk][ty * 4 + u];
#pragma unroll
                for (int v = 0; v < 4; v++) br[v] = Bs[kk][tx * 4 + v];
#pragma unroll
                for (int u = 0; u < 4; u++)
#pragma unroll
                    for (int v = 0; v < 4; v++)
                        acc[u][v] = fmaf(ar[u], br[v], acc[u][v]);
            }
        }
    }

#pragma unroll
    for (int u = 0; u < 4; u++) {
        int m = m0 + ty * 4 + u;                 // batch index
        int cls = text[m * Sz + step];
#pragma unroll
        for (int v = 0; v < 4; v++) {
            int n = n0 + tx * 4 + v;             // gate index
            g_gates[(size_t)m * (4 * Hz) + n] =
                acc[u][v] + b_ih[n] + b_hh[n] + W_ih[(size_t)n * XI + Iz + cls];
        }
    }
}

// ---------------------------------------------------------------------------
// Attention: one block per batch b.
//   e[t]   = sum_h tanh(feat[b,t,h] + hp[b,h]) * w_score[h]
//   alpha  = softmax(e)
//   ctx[i] = sum_t alpha[t] * batch_H[b,t,i]
// ---------------------------------------------------------------------------
__global__ __launch_bounds__(256) void attn_kernel(
    const float* __restrict__ batch_H, const float* __restrict__ w_score)
{
    __shared__ float hp_s[Hz];
    __shared__ float ws_s[Hz];
    __shared__ float e_s[Tz];
    __shared__ float red[8];

    const int b = blockIdx.x;
    const int tid = threadIdx.x;
    const int warp = tid >> 5, lane = tid & 31;

    for (int i = tid; i < Hz; i += 256) {
        hp_s[i] = g_hp[(size_t)b * Hz + i];
        ws_s[i] = w_score[i];
    }
    __syncthreads();

    // scores
    for (int t = warp; t < Tz; t += 8) {
        const float* fr = g_feat + ((size_t)b * Tz + t) * Hz;
        float s = 0.f;
#pragma unroll 4
        for (int h = lane; h < Hz; h += 32)
            s = fmaf(tanhf(fr[h] + hp_s[h]), ws_s[h], s);
#pragma unroll
        for (int o = 16; o; o >>= 1) s += __shfl_xor_sync(0xffffffffu, s, o);
        if (lane == 0) e_s[t] = s;
    }
    __syncthreads();

    // softmax over T=128 (threads 0..127 carry data)
    float v = (tid < Tz) ? e_s[tid] : -1e30f;
    float mval = v;
#pragma unroll
    for (int o = 16; o; o >>= 1) mval = fmaxf(mval, __shfl_xor_sync(0xffffffffu, mval, o));
    if (lane == 0) red[warp] = mval;
    __syncthreads();
    float mx = red[0];
#pragma unroll
    for (int w = 1; w < 8; w++) mx = fmaxf(mx, red[w]);
    float ex = (tid < Tz) ? __expf(v - mx) : 0.f;
    float ssum = ex;
#pragma unroll
    for (int o = 16; o; o >>= 1) ssum += __shfl_xor_sync(0xffffffffu, ssum, o);
    __syncthreads();                 // everyone done reading red
    if (lane == 0) red[warp] = ssum;
    __syncthreads();
    float tot = red[0] + red[1] + red[2] + red[3] + red[4] + red[5] + red[6] + red[7];
    if (tid < Tz) e_s[tid] = ex / tot;
    __syncthreads();

    // context
    const float* bh = batch_H + (size_t)b * Tz * Iz;
    for (int i = tid; i < Iz; i += 256) {
        float acc = 0.f;
#pragma unroll 8
        for (int t = 0; t < Tz; t++)
            acc = fmaf(e_s[t], bh[(size_t)t * Iz + i], acc);
        g_ctx[(size_t)b * Iz + i] = acc;
    }
}

// ---------------------------------------------------------------------------
// LSTM pointwise.  PyTorch gate order [i, f, g, o] along the 4H axis.
// ---------------------------------------------------------------------------
__device__ __forceinline__ float sigmoidf_(float x) {
    return 1.f / (1.f + __expf(-x));
}

__global__ __launch_bounds__(256) void lstm_kernel(int step) {
    int idx = blockIdx.x * blockDim.x + threadIdx.x;   // 0 .. B*H-1
    if (idx >= Bz * Hz) return;
    int b = idx >> 9, j = idx & (Hz - 1);
    const float* g = g_gates + (size_t)b * (4 * Hz);
    float ig = sigmoidf_(g[j]);
    float fg = sigmoidf_(g[Hz + j]);
    float gg = tanhf(g[2 * Hz + j]);
    float og = sigmoidf_(g[3 * Hz + j]);
    float c = fg * g_c[idx] + ig * gg;
    float h = og * tanhf(c);
    g_c[idx] = c;
    g_h[idx] = h;
    g_outh[((size_t)b * Sz + step) * Hz + j] = h;
}

// ---------------------------------------------------------------------------
// launch
// ---------------------------------------------------------------------------
extern "C" void kernel_launch(void* const* d_in, const int* in_sizes, int n_in,
                              void* d_out, int out_size) {
    const float* batch_H = (const float*)d_in[0];
    const int*   text    = (const int*)d_in[1];
    const float* W_feat  = (const float*)d_in[2];
    const float* W_hid   = (const float*)d_in[3];
    const float* b_hid   = (const float*)d_in[4];
    const float* w_score = (const float*)d_in[5];
    const float* W_ih    = (const float*)d_in[6];
    const float* W_hh    = (const float*)d_in[7];
    const float* b_ih    = (const float*)d_in[8];
    const float* b_hh    = (const float*)d_in[9];
    const float* W_gen   = (const float*)d_in[10];
    const float* b_gen   = (const float*)d_in[11];
    float* out = (float*)d_out;

    float *p_feat, *p_h, *p_hp, *p_outh;
    cudaGetSymbolAddress((void**)&p_feat, g_feat);
    cudaGetSymbolAddress((void**)&p_h,    g_h);
    cudaGetSymbolAddress((void**)&p_hp,   g_hp);
    cudaGetSymbolAddress((void**)&p_outh, g_outh);

    // zero h, c
    init_kernel<<<(Bz * Hz + 255) / 256, 256>>>();

    // feat = batch_H @ W_feat^T : [B*T, H]
    sgemm128<<<dim3(Hz / 128, (Bz * Tz) / 128), 256>>>(
        batch_H, W_feat, nullptr, p_feat,
        Bz * Tz, Hz, Iz, Iz, Iz, Hz);

    for (int s = 0; s < Sz; s++) {
        // hp = h @ W_hid^T + b_hid
        gemm64<<<dim3(Hz / 64, Bz / 64), 256>>>(
            p_h, W_hid, b_hid, p_hp, Hz, Hz, Hz, Hz);

        // attention + context
        attn_kernel<<<Bz, 256>>>(batch_H, w_score);

        // gates
        gates_kernel<<<dim3((4 * Hz) / 64, Bz / 64), 256>>>(
            W_ih, W_hh, b_ih, b_hh, text, s);

        // pointwise LSTM
        lstm_kernel<<<(Bz * Hz + 255) / 256, 256>>>(s);
    }

    // probs = out_h @ W_gen^T + b_gen : [B*S, C]
    sgemm128<<<dim3((Cz + 127) / 128, (Bz * Sz) / 128), 256>>>(
        p_outh, W_gen, b_gen, out,
        Bz * Sz, Cz, Hz, Hz, Hz, Cz);
}

// round 7
// speedup vs baseline: 2.2368x; 2.2368x over previous
#include <cuda_runtime.h>
#include <cuda_fp16.h>
#include <cstddef>

// Problem dims (compile-time)
#define Bz 512
#define Tz 128
#define Iz 512
#define Hz 512
#define Cz 97
#define Sz 26
#define XI (Iz + Cz)   // 609

// ---------------------------------------------------------------------------
// Scratch (device globals; no runtime allocation allowed)
// ---------------------------------------------------------------------------
__device__ alignas(16) __half g_feat16[(size_t)Bz * Tz * Hz];  // [B,T,H] fp16
__device__ alignas(16) __half g_bh16[(size_t)Bz * Tz * Iz];    // batch_H fp16
__device__ alignas(16) float g_h[Bz * Hz];
__device__ alignas(16) float g_c[Bz * Hz];
__device__ alignas(16) float g_hp[Bz * Hz];
__device__ alignas(16) float g_ctx[Bz * Iz];
__device__ alignas(16) float g_gates[Bz * 4 * Hz];
__device__ alignas(16) float g_outh[(size_t)Bz * Sz * Hz];     // [B,S,H]
__device__ alignas(16) float g_Wcat[2560 * 512];               // [W_hh ; W_hid]
__device__ alignas(16) float g_bcat[2560];                     // [b_ih+b_hh ; b_hid]
__device__ alignas(16) float g_Wih512[2048 * 512];             // W_ih[:, :512] contiguous

// ---------------------------------------------------------------------------
// init: zero h, c
// ---------------------------------------------------------------------------
__global__ void init_kernel() {
    int i = blockIdx.x * blockDim.x + threadIdx.x;
    if (i < Bz * Hz) { g_h[i] = 0.f; g_c[i] = 0.f; }
}

// ---------------------------------------------------------------------------
// one-time: batch_H fp32 -> fp16
// ---------------------------------------------------------------------------
__global__ void conv_bh_kernel(const float* __restrict__ bh) {
    size_t i = (size_t)blockIdx.x * blockDim.x + threadIdx.x;
    size_t n4 = (size_t)Bz * Tz * Iz / 4;
    if (i < n4) {
        float4 v = ((const float4*)bh)[i];
        ((__half2*)g_bh16)[2 * i]     = __floats2half2_rn(v.x, v.y);
        ((__half2*)g_bh16)[2 * i + 1] = __floats2half2_rn(v.z, v.w);
    }
}

// ---------------------------------------------------------------------------
// one-time: build concatenated recurrent weight [W_hh(2048); W_hid(512)] + bias
// ---------------------------------------------------------------------------
__global__ void prep_wcat_kernel(const float* __restrict__ W_hh,
                                 const float* __restrict__ W_hid,
                                 const float* __restrict__ b_ih,
                                 const float* __restrict__ b_hh,
                                 const float* __restrict__ b_hid) {
    int idx = blockIdx.x * blockDim.x + threadIdx.x;
    if (idx < 2560 * 512) {
        int n = idx >> 9, k = idx & 511;
        g_Wcat[idx] = (n < 2048) ? W_hh[idx] : W_hid[(n - 2048) * 512 + k];
    }
    if (idx < 2560)
        g_bcat[idx] = (idx < 2048) ? (b_ih[idx] + b_hh[idx]) : b_hid[idx - 2048];
}

// ---------------------------------------------------------------------------
// one-time: W_ih[:, :512] into contiguous [2048,512]
// ---------------------------------------------------------------------------
__global__ void prep_wih_kernel(const float* __restrict__ W_ih) {
    int idx = blockIdx.x * blockDim.x + threadIdx.x;
    if (idx < 2048 * 512) {
        int n = idx >> 9, k = idx & 511;
        g_Wih512[idx] = W_ih[(size_t)n * XI + k];
    }
}

// ---------------------------------------------------------------------------
// tf32 tensor-core GEMM:  C[m,n] = sum_k A[m,k] * B[n,k]
// Fixed K=512, lda=ldb=512.  Tile 128(M) x 64(N), BK=32, 256 threads (8 warps,
// 4 along M x 2 along N), each warp 32x32 via 2x4 m16n8k8 tf32 mma tiles.
// MODE 0: feat  -> g_feat16 (fp16), no bias
// MODE 1: h-combined -> n<2048: g_gates = acc + bcat ; n>=2048: g_hp = acc + bcat
// MODE 2: ctx   -> g_gates += acc + W_ih[n, 512+cls(m)]
// ---------------------------------------------------------------------------
__device__ __forceinline__ unsigned f2tf(float x) {
    unsigned r; asm("cvt.rna.tf32.f32 %0, %1;" : "=r"(r) : "f"(x)); return r;
}
__device__ __forceinline__ float4 f2tf4(float4 v) {
    float4 o;
    o.x = __uint_as_float(f2tf(v.x));
    o.y = __uint_as_float(f2tf(v.y));
    o.z = __uint_as_float(f2tf(v.z));
    o.w = __uint_as_float(f2tf(v.w));
    return o;
}
__device__ __forceinline__ void mma8(float* c, const unsigned* a, const unsigned* b) {
    asm volatile(
        "mma.sync.aligned.m16n8k8.row.col.f32.tf32.tf32.f32 "
        "{%0,%1,%2,%3}, {%4,%5,%6,%7}, {%8,%9}, {%0,%1,%2,%3};"
        : "+f"(c[0]), "+f"(c[1]), "+f"(c[2]), "+f"(c[3])
        : "r"(a[0]), "r"(a[1]), "r"(a[2]), "r"(a[3]), "r"(b[0]), "r"(b[1]));
}

template <int MODE>
__global__ __launch_bounds__(256) void tf32_gemm(
    const float* __restrict__ A, const float* __restrict__ B,
    const float* __restrict__ Wih_full, const int* __restrict__ text, int step)
{
    __shared__ alignas(16) float As[128][36];
    __shared__ alignas(16) float Bs[64][36];

    const int tid  = threadIdx.x;
    const int warp = tid >> 5, lane = tid & 31;
    const int wm = warp & 3, wn = warp >> 2;
    const int g  = lane >> 2, tg = lane & 3;
    const int m0 = blockIdx.y * 128, n0 = blockIdx.x * 64;

    const float* Ap = A + (size_t)(m0 + (tid >> 1)) * 512 + (tid & 1) * 16;
    const float* Bp = B + (size_t)(n0 + (tid >> 2)) * 512 + (tid & 3) * 8;

    float acc[2][4][4] = {};
    float4 ar[4], br[2];
#pragma unroll
    for (int j = 0; j < 4; j++) ar[j] = ((const float4*)Ap)[j];
#pragma unroll
    for (int j = 0; j < 2; j++) br[j] = ((const float4*)Bp)[j];

    const int arow = tid >> 1, acol = (tid & 1) * 16;
    const int brow = tid >> 2, bcol = (tid & 3) * 8;

    for (int kt = 0; kt < 16; kt++) {
#pragma unroll
        for (int j = 0; j < 4; j++)
            *(float4*)&As[arow][acol + 4 * j] = f2tf4(ar[j]);
#pragma unroll
        for (int j = 0; j < 2; j++)
            *(float4*)&Bs[brow][bcol + 4 * j] = f2tf4(br[j]);
        __syncthreads();

        if (kt < 15) {
            const float* An = Ap + (kt + 1) * 32;
            const float* Bn = Bp + (kt + 1) * 32;
#pragma unroll
            for (int j = 0; j < 4; j++) ar[j] = ((const float4*)An)[j];
#pragma unroll
            for (int j = 0; j < 2; j++) br[j] = ((const float4*)Bn)[j];
        }

#pragma unroll
        for (int ks = 0; ks < 4; ks++) {
            const int kb = ks * 8;
            unsigned af[2][4], bf[4][2];
#pragma unroll
            for (int mi = 0; mi < 2; mi++) {
                int mr = wm * 32 + mi * 16 + g;
                af[mi][0] = __float_as_uint(As[mr][kb + tg]);
                af[mi][1] = __float_as_uint(As[mr + 8][kb + tg]);
                af[mi][2] = __float_as_uint(As[mr][kb + tg + 4]);
                af[mi][3] = __float_as_uint(As[mr + 8][kb + tg + 4]);
            }
#pragma unroll
            for (int ni = 0; ni < 4; ni++) {
                int nr = wn * 32 + ni * 8 + g;
                bf[ni][0] = __float_as_uint(Bs[nr][kb + tg]);
                bf[ni][1] = __float_as_uint(Bs[nr][kb + tg + 4]);
            }
#pragma unroll
            for (int mi = 0; mi < 2; mi++)
#pragma unroll
                for (int ni = 0; ni < 4; ni++)
                    mma8(acc[mi][ni], af[mi], bf[ni]);
        }
        __syncthreads();
    }

    // epilogue
#pragma unroll
    for (int mi = 0; mi < 2; mi++) {
#pragma unroll
        for (int ni = 0; ni < 4; ni++) {
            const int m = m0 + wm * 32 + mi * 16 + g;
            const int n = n0 + wn * 32 + ni * 8 + 2 * tg;
            const float* c = acc[mi][ni];
            if (MODE == 0) {
                *(__half2*)&g_feat16[(size_t)m * 512 + n] =
                    __floats2half2_rn(c[0], c[1]);
                *(__half2*)&g_feat16[(size_t)(m + 8) * 512 + n] =
                    __floats2half2_rn(c[2], c[3]);
            } else if (MODE == 1) {
                if (n < 2048) {
                    g_gates[(size_t)m * 2048 + n]           = c[0] + g_bcat[n];
                    g_gates[(size_t)m * 2048 + n + 1]       = c[1] + g_bcat[n + 1];
                    g_gates[(size_t)(m + 8) * 2048 + n]     = c[2] + g_bcat[n];
                    g_gates[(size_t)(m + 8) * 2048 + n + 1] = c[3] + g_bcat[n + 1];
                } else {
                    int nn = n - 2048;
                    g_hp[(size_t)m * 512 + nn]           = c[0] + g_bcat[n];
                    g_hp[(size_t)m * 512 + nn + 1]       = c[1] + g_bcat[n + 1];
                    g_hp[(size_t)(m + 8) * 512 + nn]     = c[2] + g_bcat[n];
                    g_hp[(size_t)(m + 8) * 512 + nn + 1] = c[3] + g_bcat[n + 1];
                }
            } else {
                const int cls0 = text[m * Sz + step];
                const int cls1 = text[(m + 8) * Sz + step];
                size_t o0 = (size_t)m * 2048 + n;
                size_t o1 = (size_t)(m + 8) * 2048 + n;
                g_gates[o0]     += c[0] + Wih_full[(size_t)n * XI + Iz + cls0];
                g_gates[o0 + 1] += c[1] + Wih_full[(size_t)(n + 1) * XI + Iz + cls0];
                g_gates[o1]     += c[2] + Wih_full[(size_t)n * XI + Iz + cls1];
                g_gates[o1 + 1] += c[3] + Wih_full[(size_t)(n + 1) * XI + Iz + cls1];
            }
        }
    }
}

// ---------------------------------------------------------------------------
// Attention (fp16 feat + fp16 batch_H): one block per batch b.
// ---------------------------------------------------------------------------
__global__ __launch_bounds__(256) void attn_kernel(const float* __restrict__ w_score)
{
    __shared__ float hp_s[Hz];
    __shared__ float ws_s[Hz];
    __shared__ float e_s[Tz];
    __shared__ float red[8];

    const int b = blockIdx.x;
    const int tid = threadIdx.x;
    const int warp = tid >> 5, lane = tid & 31;

    for (int i = tid; i < Hz; i += 256) {
        hp_s[i] = g_hp[(size_t)b * Hz + i];
        ws_s[i] = w_score[i];
    }
    __syncthreads();

    // scores: e[t] = sum_h tanh(feat16[b,t,h] + hp[h]) * ws[h]
    for (int t = warp; t < Tz; t += 8) {
        const uint4* fr = (const uint4*)(g_feat16 + ((size_t)b * Tz + t) * Hz);
        float s = 0.f;
#pragma unroll
        for (int rep = 0; rep < 2; rep++) {
            uint4 v = fr[rep * 32 + lane];
            const int h0 = rep * 256 + lane * 8;
            const __half2* hv = (const __half2*)&v;
#pragma unroll
            for (int j = 0; j < 4; j++) {
                float2 f = __half22float2(hv[j]);
                float x0 = f.x + hp_s[h0 + 2 * j];
                float x1 = f.y + hp_s[h0 + 2 * j + 1];
                float t0, t1;
                asm("tanh.approx.f32 %0, %1;" : "=f"(t0) : "f"(x0));
                asm("tanh.approx.f32 %0, %1;" : "=f"(t1) : "f"(x1));
                s = fmaf(t0, ws_s[h0 + 2 * j], s);
                s = fmaf(t1, ws_s[h0 + 2 * j + 1], s);
            }
        }
#pragma unroll
        for (int o = 16; o; o >>= 1) s += __shfl_xor_sync(0xffffffffu, s, o);
        if (lane == 0) e_s[t] = s;
    }
    __syncthreads();

    // softmax over T=128 (threads 0..127 carry data)
    float v = (tid < Tz) ? e_s[tid] : -1e30f;
    float mval = v;
#pragma unroll
    for (int o = 16; o; o >>= 1) mval = fmaxf(mval, __shfl_xor_sync(0xffffffffu, mval, o));
    if (lane == 0) red[warp] = mval;
    __syncthreads();
    float mx = red[0];
#pragma unroll
    for (int w = 1; w < 8; w++) mx = fmaxf(mx, red[w]);
    float ex = (tid < Tz) ? __expf(v - mx) : 0.f;
    float ssum = ex;
#pragma unroll
    for (int o = 16; o; o >>= 1) ssum += __shfl_xor_sync(0xffffffffu, ssum, o);
    __syncthreads();
    if (lane == 0) red[warp] = ssum;
    __syncthreads();
    float tot = red[0] + red[1] + red[2] + red[3] + red[4] + red[5] + red[6] + red[7];
    if (tid < Tz) e_s[tid] = ex / tot;
    __syncthreads();

    // ctx[i] = sum_t alpha[t] * batch_H16[b,t,i]   (2 cols per thread via half2)
    const __half2* bh2 = (const __half2*)(g_bh16 + (size_t)b * Tz * Iz);
    float ax = 0.f, ay = 0.f;
#pragma unroll 8
    for (int t = 0; t < Tz; t++) {
        float2 f = __half22float2(bh2[(size_t)t * 256 + tid]);
        float a = e_s[t];
        ax = fmaf(a, f.x, ax);
        ay = fmaf(a, f.y, ay);
    }
    g_ctx[(size_t)b * Iz + 2 * tid]     = ax;
    g_ctx[(size_t)b * Iz + 2 * tid + 1] = ay;
}

// ---------------------------------------------------------------------------
// LSTM pointwise.  Gate order [i, f, g, o].
// ---------------------------------------------------------------------------
__device__ __forceinline__ float sigmoidf_(float x) {
    return 1.f / (1.f + __expf(-x));
}

__global__ __launch_bounds__(256) void lstm_kernel(int step) {
    int idx = blockIdx.x * blockDim.x + threadIdx.x;
    if (idx >= Bz * Hz) return;
    int b = idx >> 9, j = idx & (Hz - 1);
    const float* g = g_gates + (size_t)b * (4 * Hz);
    float ig = sigmoidf_(g[j]);
    float fg = sigmoidf_(g[Hz + j]);
    float gg = tanhf(g[2 * Hz + j]);
    float og = sigmoidf_(g[3 * Hz + j]);
    float c = fg * g_c[idx] + ig * gg;
    float h = og * tanhf(c);
    g_c[idx] = c;
    g_h[idx] = h;
    g_outh[((size_t)b * Sz + step) * Hz + j] = h;
}

// ---------------------------------------------------------------------------
// fp32 SGEMM (guarded) for the small generator GEMM: C = A@B^T + bias
// ---------------------------------------------------------------------------
__global__ __launch_bounds__(256) void sgemm128(
    const float* __restrict__ A, const float* __restrict__ B,
    const float* __restrict__ bias, float* __restrict__ C,
    int M, int N, int K, int lda, int ldb, int ldc)
{
    __shared__ float As[8][128];
    __shared__ float Bs[8][128];
    const int tid = threadIdx.x;
    const int m0 = blockIdx.y * 128;
    const int n0 = blockIdx.x * 128;
    const int lr = tid >> 1;
    const int lc = (tid & 1) << 2;
    const int tx = tid & 15;
    const int ty = tid >> 4;

    float acc[8][8];
#pragma unroll
    for (int u = 0; u < 8; u++)
#pragma unroll
        for (int v = 0; v < 8; v++) acc[u][v] = 0.f;

    const int am = m0 + lr;
    const int bn = n0 + lr;

    for (int k0 = 0; k0 < K; k0 += 8) {
        float4 a4 = make_float4(0.f, 0.f, 0.f, 0.f);
        float4 b4 = make_float4(0.f, 0.f, 0.f, 0.f);
        if (am < M) a4 = *(const float4*)(A + (size_t)am * lda + k0 + lc);
        if (bn < N) b4 = *(const float4*)(B + (size_t)bn * ldb + k0 + lc);
        __syncthreads();
        As[lc + 0][lr] = a4.x; As[lc + 1][lr] = a4.y;
        As[lc + 2][lr] = a4.z; As[lc + 3][lr] = a4.w;
        Bs[lc + 0][lr] = b4.x; Bs[lc + 1][lr] = b4.y;
        Bs[lc + 2][lr] = b4.z; Bs[lc + 3][lr] = b4.w;
        __syncthreads();
#pragma unroll
        for (int kk = 0; kk < 8; kk++) {
            float4 a0 = *(const float4*)&As[kk][ty * 8];
            float4 a1 = *(const float4*)&As[kk][ty * 8 + 4];
            float4 b0 = *(const float4*)&Bs[kk][tx * 8];
            float4 b1 = *(const float4*)&Bs[kk][tx * 8 + 4];
            float arr[8] = {a0.x, a0.y, a0.z, a0.w, a1.x, a1.y, a1.z, a1.w};
            float brr[8] = {b0.x, b0.y, b0.z, b0.w, b1.x, b1.y, b1.z, b1.w};
#pragma unroll
            for (int u = 0; u < 8; u++)
#pragma unroll
                for (int v = 0; v < 8; v++)
                    acc[u][v] = fmaf(arr[u], brr[v], acc[u][v]);
        }
    }

#pragma unroll
    for (int u = 0; u < 8; u++) {
        int m = m0 + ty * 8 + u;
        if (m >= M) continue;
#pragma unroll
        for (int v = 0; v < 8; v++) {
            int n = n0 + tx * 8 + v;
            if (n < N) {
                float bv = bias ? bias[n] : 0.f;
                C[(size_t)m * ldc + n] = acc[u][v] + bv;
            }
        }
    }
}

// ---------------------------------------------------------------------------
// launch
// ---------------------------------------------------------------------------
extern "C" void kernel_launch(void* const* d_in, const int* in_sizes, int n_in,
                              void* d_out, int out_size) {
    const float* batch_H = (const float*)d_in[0];
    const int*   text    = (const int*)d_in[1];
    const float* W_feat  = (const float*)d_in[2];
    const float* W_hid   = (const float*)d_in[3];
    const float* b_hid   = (const float*)d_in[4];
    const float* w_score = (const float*)d_in[5];
    const float* W_ih    = (const float*)d_in[6];
    const float* W_hh    = (const float*)d_in[7];
    const float* b_ih    = (const float*)d_in[8];
    const float* b_hh    = (const float*)d_in[9];
    const float* W_gen   = (const float*)d_in[10];
    const float* b_gen   = (const float*)d_in[11];
    float* out = (float*)d_out;

    float *p_h, *p_ctx, *p_wcat, *p_wih512, *p_outh;
    cudaGetSymbolAddress((void**)&p_h,      g_h);
    cudaGetSymbolAddress((void**)&p_ctx,    g_ctx);
    cudaGetSymbolAddress((void**)&p_wcat,   g_Wcat);
    cudaGetSymbolAddress((void**)&p_wih512, g_Wih512);
    cudaGetSymbolAddress((void**)&p_outh,   g_outh);

    // one-time prep
    init_kernel<<<(Bz * Hz + 255) / 256, 256>>>();
    conv_bh_kernel<<<(int)(((size_t)Bz * Tz * Iz / 4 + 255) / 256), 256>>>(batch_H);
    prep_wcat_kernel<<<(2560 * 512 + 255) / 256, 256>>>(W_hh, W_hid, b_ih, b_hh, b_hid);
    prep_wih_kernel<<<(2048 * 512 + 255) / 256, 256>>>(W_ih);

    // feat16 = fp16(batch_H @ W_feat^T) : [B*T, H]
    tf32_gemm<0><<<dim3(Hz / 64, (Bz * Tz) / 128), 256>>>(
        batch_H, W_feat, nullptr, nullptr, 0);

    for (int s = 0; s < Sz; s++) {
        // gates_h = h@W_hh^T (+biases), hp = h@W_hid^T + b_hid  (one GEMM, N=2560)
        tf32_gemm<1><<<dim3(2560 / 64, Bz / 128), 256>>>(
            p_h, p_wcat, nullptr, nullptr, 0);

        // attention + context
        attn_kernel<<<Bz, 256>>>(w_score);

        // gates += ctx@W_ih[:, :512]^T + one-hot column
        tf32_gemm<2><<<dim3(2048 / 64, Bz / 128), 256>>>(
            p_ctx, p_wih512, W_ih, text, s);

        // pointwise LSTM
        lstm_kernel<<<(Bz * Hz + 255) / 256, 256>>>(s);
    }

    // probs = out_h @ W_gen^T + b_gen : [B*S, C]
    sgemm128<<<dim3((Cz + 127) / 128, (Bz * Sz) / 128), 256>>>(
        p_outh, W_gen, b_gen, out,
        Bz * Sz, Cz, Hz, Hz, Hz, Cz);
}

// round 8
// speedup vs baseline: 3.2436x; 1.4501x over previous
#include <cuda_runtime.h>
#include <cuda_fp16.h>
#include <cstddef>

// Problem dims (compile-time)
#define Bz 512
#define Tz 128
#define Iz 512
#define Hz 512
#define Cz 97
#define Sz 26
#define XI (Iz + Cz)   // 609

// ---------------------------------------------------------------------------
// Scratch (device globals; no runtime allocation allowed)
// ---------------------------------------------------------------------------
__device__ alignas(16) __half g_feat16[(size_t)Bz * Tz * Hz];  // [B,T,H] fp16
__device__ alignas(16) __half g_bh16[(size_t)Bz * Tz * Iz];    // batch_H fp16
__device__ alignas(16) __half g_h16[Bz * Hz];                  // hidden state fp16
__device__ alignas(16) float  g_c[Bz * Hz];                    // cell state fp32
__device__ alignas(16) float  g_hp[Bz * Hz];                   // hidden proj fp32
__device__ alignas(16) __half g_ctx16[Bz * Iz];                // context fp16
__device__ alignas(16) float  g_gates[Bz * 2048];              // h-part of gates (PERMUTED n'=4j+g)
__device__ alignas(16) __half g_outh16[(size_t)Bz * Sz * Hz];  // [B,S,H] fp16
__device__ alignas(16) __half g_Wcat16[2560 * 512];            // [perm(W_hh) ; W_hid] fp16
__device__ alignas(16) float  g_bcat[2560];                    // [perm(b_ih+b_hh) ; b_hid]
__device__ alignas(16) __half g_Wih16[2048 * 512];             // perm(W_ih[:, :512]) fp16
__device__ alignas(16) __half g_Wfeat16[512 * 512];            // W_feat fp16
__device__ alignas(16) __half g_Wgen16[128 * 512];             // W_gen padded to 128 rows fp16

// ---------------------------------------------------------------------------
// init: zero h16, c
// ---------------------------------------------------------------------------
__global__ void init_kernel() {
    int i = blockIdx.x * blockDim.x + threadIdx.x;
    if (i < Bz * Hz) { g_h16[i] = __float2half(0.f); g_c[i] = 0.f; }
}

// ---------------------------------------------------------------------------
// one-time: batch_H fp32 -> fp16
// ---------------------------------------------------------------------------
__global__ void conv_bh_kernel(const float* __restrict__ bh) {
    size_t i = (size_t)blockIdx.x * blockDim.x + threadIdx.x;
    size_t n4 = (size_t)Bz * Tz * Iz / 4;
    if (i < n4) {
        float4 v = ((const float4*)bh)[i];
        ((__half2*)g_bh16)[2 * i]     = __floats2half2_rn(v.x, v.y);
        ((__half2*)g_bh16)[2 * i + 1] = __floats2half2_rn(v.z, v.w);
    }
}

// permutation: n' in [0,2048) -> original gate row = (n'&3)*512 + (n'>>2)
__device__ __forceinline__ int orig_row(int np) { return (np & 3) * 512 + (np >> 2); }

// one-time: Wcat16 = [perm(W_hh)(2048) ; W_hid(512)] fp16, bcat permuted
__global__ void prep_wcat_kernel(const float* __restrict__ W_hh,
                                 const float* __restrict__ W_hid,
                                 const float* __restrict__ b_ih,
                                 const float* __restrict__ b_hh,
                                 const float* __restrict__ b_hid) {
    int idx = blockIdx.x * blockDim.x + threadIdx.x;
    if (idx < 2560 * 512) {
        int n = idx >> 9, k = idx & 511;
        float v = (n < 2048) ? W_hh[(size_t)orig_row(n) * 512 + k]
                             : W_hid[(size_t)(n - 2048) * 512 + k];
        g_Wcat16[idx] = __float2half(v);
    }
    if (idx < 2560) {
        g_bcat[idx] = (idx < 2048) ? (b_ih[orig_row(idx)] + b_hh[orig_row(idx)])
                                   : b_hid[idx - 2048];
    }
}

// one-time: perm(W_ih[:, :512]) fp16
__global__ void prep_wih_kernel(const float* __restrict__ W_ih) {
    int idx = blockIdx.x * blockDim.x + threadIdx.x;
    if (idx < 2048 * 512) {
        int n = idx >> 9, k = idx & 511;
        g_Wih16[idx] = __float2half(W_ih[(size_t)orig_row(n) * XI + k]);
    }
}

// one-time: W_feat fp16
__global__ void prep_wfeat_kernel(const float* __restrict__ W_feat) {
    int idx = blockIdx.x * blockDim.x + threadIdx.x;
    if (idx < 512 * 512) g_Wfeat16[idx] = __float2half(W_feat[idx]);
}

// one-time: W_gen fp16 padded to 128 rows
__global__ void prep_wgen_kernel(const float* __restrict__ W_gen) {
    int idx = blockIdx.x * blockDim.x + threadIdx.x;
    if (idx < 128 * 512) {
        int n = idx >> 9, k = idx & 511;
        g_Wgen16[idx] = __float2half((n < Cz) ? W_gen[(size_t)n * 512 + k] : 0.f);
    }
}

// ---------------------------------------------------------------------------
// fp16 tensor-core GEMM:  C[m,n] = sum_k A[m,k] * B[n,k]   (K=512 fixed)
// Tile 128(M) x 64(N), BK=32 halves, 256 threads, 8 warps (4m x 2n),
// warp tile 32x32 via 2x4 m16n8k16 f16 mma, fp32 accumulate.
// MODE 0: feat -> g_feat16
// MODE 1: h-combined -> n<2048: g_gates = acc + bcat (permuted); else g_hp
// MODE 2: ctx-part + fused LSTM pointwise (permuted gate layout)
// MODE 3: generator -> out fp32, guard n < 97
// ---------------------------------------------------------------------------
__device__ __forceinline__ void mma16(float* c, const unsigned* a, const unsigned* b) {
    asm volatile(
        "mma.sync.aligned.m16n8k16.row.col.f32.f16.f16.f32 "
        "{%0,%1,%2,%3}, {%4,%5,%6,%7}, {%8,%9}, {%0,%1,%2,%3};"
        : "+f"(c[0]), "+f"(c[1]), "+f"(c[2]), "+f"(c[3])
        : "r"(a[0]), "r"(a[1]), "r"(a[2]), "r"(a[3]), "r"(b[0]), "r"(b[1]));
}

__device__ __forceinline__ float sigmoidf_(float x) {
    return 1.f / (1.f + __expf(-x));
}

template <int MODE>
__global__ __launch_bounds__(256) void h16gemm(
    const __half* __restrict__ A, const __half* __restrict__ B,
    const float* __restrict__ Wih_full, const int* __restrict__ text,
    const float* __restrict__ bias, float* __restrict__ Cout, int step)
{
    // uint32-unit smem (each uint32 = half2), row stride 20 (16 data + 4 pad)
    __shared__ unsigned As2[128][20];
    __shared__ unsigned Bs2[64][20];

    const int tid  = threadIdx.x;
    const int warp = tid >> 5, lane = tid & 31;
    const int wm = warp & 3, wn = warp >> 2;
    const int g  = lane >> 2, tg = lane & 3;
    const int m0 = blockIdx.y * 128, n0 = blockIdx.x * 64;

    // loaders: A tile 128 rows x 32 halves (2 uint4/thread), B tile 64 x 32 (1 uint4)
    const int ar0 = tid >> 2, aq = tid & 3;
    const __half* Ap0 = A + (size_t)(m0 + ar0) * 512 + aq * 8;
    const __half* Ap1 = A + (size_t)(m0 + ar0 + 64) * 512 + aq * 8;
    const __half* Bp  = B + (size_t)(n0 + (tid >> 2)) * 512 + (tid & 3) * 8;

    float acc[2][4][4] = {};
    uint4 ra0 = *(const uint4*)Ap0;
    uint4 ra1 = *(const uint4*)Ap1;
    uint4 rb  = *(const uint4*)Bp;

    for (int kt = 0; kt < 16; kt++) {
        *(uint4*)&As2[ar0][aq * 4]      = ra0;
        *(uint4*)&As2[ar0 + 64][aq * 4] = ra1;
        *(uint4*)&Bs2[tid >> 2][(tid & 3) * 4] = rb;
        __syncthreads();

        if (kt < 15) {
            ra0 = *(const uint4*)(Ap0 + (kt + 1) * 32);
            ra1 = *(const uint4*)(Ap1 + (kt + 1) * 32);
            rb  = *(const uint4*)(Bp + (kt + 1) * 32);
        }

#pragma unroll
        for (int ks = 0; ks < 2; ks++) {
            const int kb = ks * 8;
            unsigned af[2][4], bf[4][2];
#pragma unroll
            for (int mi = 0; mi < 2; mi++) {
                int mr = wm * 32 + mi * 16 + g;
                af[mi][0] = As2[mr][kb + tg];
                af[mi][1] = As2[mr + 8][kb + tg];
                af[mi][2] = As2[mr][kb + tg + 4];
                af[mi][3] = As2[mr + 8][kb + tg + 4];
            }
#pragma unroll
            for (int ni = 0; ni < 4; ni++) {
                int nr = wn * 32 + ni * 8 + g;
                bf[ni][0] = Bs2[nr][kb + tg];
                bf[ni][1] = Bs2[nr][kb + tg + 4];
            }
#pragma unroll
            for (int mi = 0; mi < 2; mi++)
#pragma unroll
                for (int ni = 0; ni < 4; ni++)
                    mma16(acc[mi][ni], af[mi], bf[ni]);
        }
        __syncthreads();
    }

    // epilogue
#pragma unroll
    for (int mi = 0; mi < 2; mi++) {
#pragma unroll
        for (int ni = 0; ni < 4; ni++) {
            const int m = m0 + wm * 32 + mi * 16 + g;
            const int n = n0 + wn * 32 + ni * 8 + 2 * tg;
            const float* c = acc[mi][ni];

            if (MODE == 0) {
                *(__half2*)&g_feat16[(size_t)m * 512 + n] =
                    __floats2half2_rn(c[0], c[1]);
                *(__half2*)&g_feat16[(size_t)(m + 8) * 512 + n] =
                    __floats2half2_rn(c[2], c[3]);
            } else if (MODE == 1) {
                if (n < 2048) {
                    g_gates[(size_t)m * 2048 + n]           = c[0] + g_bcat[n];
                    g_gates[(size_t)m * 2048 + n + 1]       = c[1] + g_bcat[n + 1];
                    g_gates[(size_t)(m + 8) * 2048 + n]     = c[2] + g_bcat[n];
                    g_gates[(size_t)(m + 8) * 2048 + n + 1] = c[3] + g_bcat[n + 1];
                } else {
                    int nn = n - 2048;
                    g_hp[(size_t)m * 512 + nn]           = c[0] + g_bcat[n];
                    g_hp[(size_t)m * 512 + nn + 1]       = c[1] + g_bcat[n + 1];
                    g_hp[(size_t)(m + 8) * 512 + nn]     = c[2] + g_bcat[n];
                    g_hp[(size_t)(m + 8) * 512 + nn + 1] = c[3] + g_bcat[n + 1];
                }
            } else if (MODE == 2) {
                // full gate pre-activations (permuted layout n' = 4j + gate)
                const int cls0 = text[m * Sz + step];
                const int cls1 = text[(m + 8) * Sz + step];
                float v0 = c[0] + g_gates[(size_t)m * 2048 + n]
                         + Wih_full[(size_t)orig_row(n) * XI + Iz + cls0];
                float v1 = c[1] + g_gates[(size_t)m * 2048 + n + 1]
                         + Wih_full[(size_t)orig_row(n + 1) * XI + Iz + cls0];
                float v2 = c[2] + g_gates[(size_t)(m + 8) * 2048 + n]
                         + Wih_full[(size_t)orig_row(n) * XI + Iz + cls1];
                float v3 = c[3] + g_gates[(size_t)(m + 8) * 2048 + n + 1]
                         + Wih_full[(size_t)orig_row(n + 1) * XI + Iz + cls1];

                // lane-pair exchange: tg even holds (i,f), tg odd holds (g,o) of same j
                float o0 = __shfl_xor_sync(0xffffffffu, v0, 1);
                float o1 = __shfl_xor_sync(0xffffffffu, v1, 1);
                float o2 = __shfl_xor_sync(0xffffffffu, v2, 1);
                float o3 = __shfl_xor_sync(0xffffffffu, v3, 1);

                const int j = n >> 2;     // same for the lane pair
                int row; float i_, f_, g_, q_;
                if ((tg & 1) == 0) {      // even lane: row m
                    row = m;     i_ = v0; f_ = v1; g_ = o0; q_ = o1;
                } else {                  // odd lane: row m+8
                    row = m + 8; i_ = o2; f_ = o3; g_ = v2; q_ = v3;
                }
                float cp = g_c[row * 512 + j];
                float ig = sigmoidf_(i_);
                float fg = sigmoidf_(f_);
                float gg = tanhf(g_);
                float og = sigmoidf_(q_);
                float cn = fg * cp + ig * gg;
                float hn = og * tanhf(cn);
                g_c[row * 512 + j] = cn;
                __half hh = __float2half(hn);
                g_h16[row * 512 + j] = hh;
                g_outh16[((size_t)row * Sz + step) * 512 + j] = hh;
            } else {  // MODE 3: generator
                if (n < Cz) {
                    Cout[(size_t)m * Cz + n]       = c[0] + bias[n];
                    Cout[(size_t)(m + 8) * Cz + n] = c[2] + bias[n];
                }
                if (n + 1 < Cz) {
                    Cout[(size_t)m * Cz + n + 1]       = c[1] + bias[n + 1];
                    Cout[(size_t)(m + 8) * Cz + n + 1] = c[3] + bias[n + 1];
                }
            }
        }
    }
}

// ---------------------------------------------------------------------------
// Attention (fp16 feat + fp16 batch_H): one block per batch b.
// ---------------------------------------------------------------------------
__global__ __launch_bounds__(256) void attn_kernel(const float* __restrict__ w_score)
{
    __shared__ float hp_s[Hz];
    __shared__ float ws_s[Hz];
    __shared__ float e_s[Tz];
    __shared__ float red[8];

    const int b = blockIdx.x;
    const int tid = threadIdx.x;
    const int warp = tid >> 5, lane = tid & 31;

    for (int i = tid; i < Hz; i += 256) {
        hp_s[i] = g_hp[(size_t)b * Hz + i];
        ws_s[i] = w_score[i];
    }
    __syncthreads();

    // scores: e[t] = sum_h tanh(feat16[b,t,h] + hp[h]) * ws[h]
    for (int t = warp; t < Tz; t += 8) {
        const uint4* fr = (const uint4*)(g_feat16 + ((size_t)b * Tz + t) * Hz);
        float s = 0.f;
#pragma unroll
        for (int rep = 0; rep < 2; rep++) {
            uint4 v = fr[rep * 32 + lane];
            const int h0 = rep * 256 + lane * 8;
            const __half2* hv = (const __half2*)&v;
#pragma unroll
            for (int j = 0; j < 4; j++) {
                float2 f = __half22float2(hv[j]);
                float x0 = f.x + hp_s[h0 + 2 * j];
                float x1 = f.y + hp_s[h0 + 2 * j + 1];
                float t0, t1;
                asm("tanh.approx.f32 %0, %1;" : "=f"(t0) : "f"(x0));
                asm("tanh.approx.f32 %0, %1;" : "=f"(t1) : "f"(x1));
                s = fmaf(t0, ws_s[h0 + 2 * j], s);
                s = fmaf(t1, ws_s[h0 + 2 * j + 1], s);
            }
        }
#pragma unroll
        for (int o = 16; o; o >>= 1) s += __shfl_xor_sync(0xffffffffu, s, o);
        if (lane == 0) e_s[t] = s;
    }
    __syncthreads();

    // softmax over T=128
    float v = (tid < Tz) ? e_s[tid] : -1e30f;
    float mval = v;
#pragma unroll
    for (int o = 16; o; o >>= 1) mval = fmaxf(mval, __shfl_xor_sync(0xffffffffu, mval, o));
    if (lane == 0) red[warp] = mval;
    __syncthreads();
    float mx = red[0];
#pragma unroll
    for (int w = 1; w < 8; w++) mx = fmaxf(mx, red[w]);
    float ex = (tid < Tz) ? __expf(v - mx) : 0.f;
    float ssum = ex;
#pragma unroll
    for (int o = 16; o; o >>= 1) ssum += __shfl_xor_sync(0xffffffffu, ssum, o);
    __syncthreads();
    if (lane == 0) red[warp] = ssum;
    __syncthreads();
    float tot = red[0] + red[1] + red[2] + red[3] + red[4] + red[5] + red[6] + red[7];
    if (tid < Tz) e_s[tid] = ex / tot;
    __syncthreads();

    // ctx[i] = sum_t alpha[t] * batch_H16[b,t,i]  -> fp16 ctx
    const __half2* bh2 = (const __half2*)(g_bh16 + (size_t)b * Tz * Iz);
    float ax = 0.f, ay = 0.f;
#pragma unroll 8
    for (int t = 0; t < Tz; t++) {
        float2 f = __half22float2(bh2[(size_t)t * 256 + tid]);
        float a = e_s[t];
        ax = fmaf(a, f.x, ax);
        ay = fmaf(a, f.y, ay);
    }
    *(__half2*)&g_ctx16[(size_t)b * Iz + 2 * tid] = __floats2half2_rn(ax, ay);
}

// ---------------------------------------------------------------------------
// launch
// ---------------------------------------------------------------------------
extern "C" void kernel_launch(void* const* d_in, const int* in_sizes, int n_in,
                              void* d_out, int out_size) {
    const float* batch_H = (const float*)d_in[0];
    const int*   text    = (const int*)d_in[1];
    const float* W_feat  = (const float*)d_in[2];
    const float* W_hid   = (const float*)d_in[3];
    const float* b_hid   = (const float*)d_in[4];
    const float* w_score = (const float*)d_in[5];
    const float* W_ih    = (const float*)d_in[6];
    const float* W_hh    = (const float*)d_in[7];
    const float* b_ih    = (const float*)d_in[8];
    const float* b_hh    = (const float*)d_in[9];
    const float* W_gen   = (const float*)d_in[10];
    const float* b_gen   = (const float*)d_in[11];
    float* out = (float*)d_out;

    __half *p_bh16, *p_h16, *p_ctx16, *p_outh16, *p_wcat16, *p_wih16, *p_wfeat16, *p_wgen16;
    cudaGetSymbolAddress((void**)&p_bh16,    g_bh16);
    cudaGetSymbolAddress((void**)&p_h16,     g_h16);
    cudaGetSymbolAddress((void**)&p_ctx16,   g_ctx16);
    cudaGetSymbolAddress((void**)&p_outh16,  g_outh16);
    cudaGetSymbolAddress((void**)&p_wcat16,  g_Wcat16);
    cudaGetSymbolAddress((void**)&p_wih16,   g_Wih16);
    cudaGetSymbolAddress((void**)&p_wfeat16, g_Wfeat16);
    cudaGetSymbolAddress((void**)&p_wgen16,  g_Wgen16);

    // one-time prep
    init_kernel<<<(Bz * Hz + 255) / 256, 256>>>();
    conv_bh_kernel<<<(int)(((size_t)Bz * Tz * Iz / 4 + 255) / 256), 256>>>(batch_H);
    prep_wcat_kernel<<<(2560 * 512 + 255) / 256, 256>>>(W_hh, W_hid, b_ih, b_hh, b_hid);
    prep_wih_kernel<<<(2048 * 512 + 255) / 256, 256>>>(W_ih);
    prep_wfeat_kernel<<<(512 * 512 + 255) / 256, 256>>>(W_feat);
    prep_wgen_kernel<<<(128 * 512 + 255) / 256, 256>>>(W_gen);

    // feat16 = fp16(batch_H @ W_feat^T) : [B*T, H]
    h16gemm<0><<<dim3(Hz / 64, (Bz * Tz) / 128), 256>>>(
        p_bh16, p_wfeat16, nullptr, nullptr, nullptr, nullptr, 0);

    for (int s = 0; s < Sz; s++) {
        // gates_h (permuted) = h@perm(W_hh)^T + biases ; hp = h@W_hid^T + b_hid
        h16gemm<1><<<dim3(2560 / 64, Bz / 128), 256>>>(
            p_h16, p_wcat16, nullptr, nullptr, nullptr, nullptr, 0);

        // attention + context (fp16 ctx)
        attn_kernel<<<Bz, 256>>>(w_score);

        // gates += ctx@perm(W_ih)^T + one-hot col, then fused LSTM pointwise
        h16gemm<2><<<dim3(2048 / 64, Bz / 128), 256>>>(
            p_ctx16, p_wih16, W_ih, text, nullptr, nullptr, s);
    }

    // probs = out_h @ W_gen^T + b_gen : [B*S, C]
    h16gemm<3><<<dim3(2, (Bz * Sz) / 128), 256>>>(
        p_outh16, p_wgen16, nullptr, nullptr, b_gen, out, 0);
}